// round 12
// baseline (speedup 1.0000x reference)
#include <cuda_runtime.h>
#include <cstdint>

// CIN (xDeepFM) via mma.sync m16n8k16 fp16 — round 12.
// R11 + prefetch.global.L1 (distance 2 ksteps) on the A stream + padded W
// arrays (no tail select). Barrier-free LDG mainloop, fp16-packed Xi/X0 smem,
// register epilogue. 512 thr, 64h x 32n warp tiles.

#define THREADS 512
#define NBT     16
#define XR2     264    // uint32 row stride for packed fp16 buffers; mod 32 == 8

// Fragment-ordered fp16 weights (+512 uint4 pad for tail loads/prefetch):
// [chunk][k16step][hgroup(2)][mtile(4)][lane(32)] uint4
__device__ uint4 W0f[39 * 3 * 2 * 4 * 32 + 512];
__device__ uint4 W1f[156 * 2 * 2 * 4 * 32 + 512];
__device__ uint4 W2f[156 * 2 * 2 * 4 * 32 + 512];

__device__ __forceinline__ uint32_t pk16(float lo, float hi) {
    uint32_t r; asm("cvt.rn.f16x2.f32 %0, %1, %2;" : "=r"(r) : "f"(hi), "f"(lo));
    return r;
}
__device__ __forceinline__ uint32_t hmul2(uint32_t a, uint32_t b) {
    uint32_t r; asm("mul.rn.f16x2 %0, %1, %2;" : "=r"(r) : "r"(a), "r"(b));
    return r;
}
__device__ __forceinline__ uint32_t prmt(uint32_t a, uint32_t sel) {
    uint32_t r; asm("prmt.b32 %0, %1, %2, %3;" : "=r"(r) : "r"(a), "r"(a), "r"(sel));
    return r;
}
__device__ __forceinline__ void pf_l1(const void* p) {
    asm volatile("prefetch.global.L1 [%0];" :: "l"(p));
}
__device__ __forceinline__ void mma16(float c[4], const uint4 a, uint32_t b0, uint32_t b1) {
    asm volatile(
        "mma.sync.aligned.m16n8k16.row.col.f32.f16.f16.f32 "
        "{%0,%1,%2,%3},{%4,%5,%6,%7},{%8,%9},{%0,%1,%2,%3};"
        : "+f"(c[0]), "+f"(c[1]), "+f"(c[2]), "+f"(c[3])
        : "r"(a.x), "r"(a.y), "r"(a.z), "r"(a.w), "r"(b0), "r"(b1));
}

// -------------------- weight prep: fragment repack [c][ks][hg][mt][lane] -------
__global__ void frag_w(const float* __restrict__ W, uint4* __restrict__ Wo) {
    int g = blockIdx.x * 256 + threadIdx.x;
    if (g >= 156 * 512) return;
    int lane = g & 31, mt = (g >> 5) & 3, hg = (g >> 7) & 1, ks = (g >> 8) & 1, c = g >> 9;
    int grp = lane >> 2, tig = lane & 3;
    int r0 = (hg * 4 + mt) * 16 + grp, r1 = r0 + 8;
    int kc = c * 32 + ks * 16 + 2 * tig;
    uint4 v;
    v.x = pk16(W[(size_t)r0 * 4992 + kc],     W[(size_t)r0 * 4992 + kc + 1]);
    v.y = pk16(W[(size_t)r1 * 4992 + kc],     W[(size_t)r1 * 4992 + kc + 1]);
    v.z = pk16(W[(size_t)r0 * 4992 + kc + 8], W[(size_t)r0 * 4992 + kc + 9]);
    v.w = pk16(W[(size_t)r1 * 4992 + kc + 8], W[(size_t)r1 * 4992 + kc + 9]);
    Wo[g] = v;
}
__global__ void frag_w0(const float* __restrict__ W) {
    int g = blockIdx.x * 256 + threadIdx.x;
    if (g >= 39 * 768) return;
    int lane = g & 31, mt = (g >> 5) & 3, hg = (g >> 7) & 1;
    int rest = g >> 8;
    int ks = rest % 3, c = rest / 3;
    int grp = lane >> 2, tig = lane & 3;
    int r0 = (hg * 4 + mt) * 16 + grp, r1 = r0 + 8;
    int kp = ks * 16 + 2 * tig;
    const float* w0 = W + (size_t)r0 * 1521 + c * 39;
    const float* w1 = W + (size_t)r1 * 1521 + c * 39;
    auto gv = [&](const float* w, int k) { return (k < 39) ? w[k] : 0.f; };
    uint4 v;
    v.x = pk16(gv(w0, kp),     gv(w0, kp + 1));
    v.y = pk16(gv(w1, kp),     gv(w1, kp + 1));
    v.z = pk16(gv(w0, kp + 8), gv(w0, kp + 9));
    v.w = pk16(gv(w1, kp + 8), gv(w1, kp + 9));
    W0f[g] = v;
}

// -------------------- layers 1/2: barrier-free, A double-buffered + L1 prefetch
__device__ __forceinline__ void layer12(
    const uint4* __restrict__ Wg,
    const uint32_t* xih, const uint32_t* x0h,
    float acc[4][4][4],
    int lane, int hg, int n_base, int grp, int tig)
{
    const uint4* wp = Wg + hg * 128 + lane;   // step 0; +256 uint4 per kstep
    uint4 A[2][4];
    #pragma unroll
    for (int mt = 0; mt < 4; mt++) A[0][mt] = __ldg(wp + mt * 32);
    #pragma unroll
    for (int mt = 0; mt < 4; mt++) pf_l1(wp + 256 + mt * 32);

    #pragma unroll 1
    for (int j = 0; j < 39; j++) {
        uint32_t sel = (j & 1) ? 0x3232u : 0x1010u;
        const uint32_t* x0r = x0h + (j >> 1) * XR2 + n_base + grp;
        uint32_t x0p[4];
        #pragma unroll
        for (int nt = 0; nt < 4; nt++) x0p[nt] = prmt(x0r[nt * 8], sel);

        #pragma unroll
        for (int s = 0; s < 8; s++) {            // 8 ksteps per j (parity = s&1)
            int p = s & 1;
            // load next kstep's A (pad makes tail loads safe)
            #pragma unroll
            for (int mt = 0; mt < 4; mt++) A[p ^ 1][mt] = __ldg(wp + 256 + mt * 32);
            // prefetch 2 ksteps ahead into L1
            #pragma unroll
            for (int mt = 0; mt < 4; mt++) pf_l1(wp + 512 + mt * 32);
            wp += 256;

            const uint32_t* xr = xih + (s * 8 + tig) * XR2 + n_base + grp;
            #pragma unroll
            for (int nt = 0; nt < 4; nt++) {
                uint32_t b0 = hmul2(x0p[nt], xr[nt * 8]);
                uint32_t b1 = hmul2(x0p[nt], xr[4 * XR2 + nt * 8]);
                #pragma unroll
                for (int mt = 0; mt < 4; mt++)
                    mma16(acc[mt][nt], A[p][mt], b0, b1);
            }
        }
    }
}

// -------------------- layer 0: barrier-free, direct A loads + prefetch --------
__device__ __forceinline__ void layer0(
    const uint4* __restrict__ Wg,
    const uint32_t* x0h,
    float acc[4][4][4],
    int lane, int hg, int n_base, int grp, int tig)
{
    const uint4* wp = Wg + hg * 128 + lane;

    #pragma unroll 1
    for (int j = 0; j < 39; j++) {
        uint32_t sel = (j & 1) ? 0x3232u : 0x1010u;
        const uint32_t* x0r = x0h + (j >> 1) * XR2 + n_base + grp;
        uint32_t x0p[4];
        #pragma unroll
        for (int nt = 0; nt < 4; nt++) x0p[nt] = prmt(x0r[nt * 8], sel);

        #pragma unroll
        for (int ks = 0; ks < 3; ks++) {
            uint4 A[4];
            #pragma unroll
            for (int mt = 0; mt < 4; mt++) A[mt] = __ldg(wp + mt * 32);
            #pragma unroll
            for (int mt = 0; mt < 4; mt++) pf_l1(wp + 512 + mt * 32);
            wp += 256;

            const uint32_t* xr = x0h + (ks * 8 + tig) * XR2 + n_base + grp;
            #pragma unroll
            for (int nt = 0; nt < 4; nt++) {
                uint32_t b0 = hmul2(x0p[nt], xr[nt * 8]);
                uint32_t b1 = hmul2(x0p[nt], xr[4 * XR2 + nt * 8]);
                #pragma unroll
                for (int mt = 0; mt < 4; mt++)
                    mma16(acc[mt][nt], A[mt], b0, b1);
            }
        }
    }
}

// -------------------- main fused kernel ---------------------------------------
__global__ void __launch_bounds__(THREADS)
cin_mma(const float* __restrict__ x,
        const uint4* __restrict__ w0f, const uint4* __restrict__ w1f,
        const uint4* __restrict__ w2f,
        const float* __restrict__ b0, const float* __restrict__ b1,
        const float* __restrict__ b2,
        float* __restrict__ out)
{
    extern __shared__ uint32_t smu[];
    uint32_t* x0h = smu;                 // 24 pair-rows x XR2 (X0 fp16, rows>=39 zero)
    uint32_t* xih = smu + 24 * XR2;      // 64 pair-rows x XR2 (Xi fp16)

    int tid = threadIdx.x;
    int lane = tid & 31, wid = tid >> 5;
    int grp = lane >> 2, tig = lane & 3;
    int hg = wid & 1;
    int h_base = hg * 64, n_base = (wid >> 1) * 32;
    int bbase = blockIdx.x * NBT;

    // build packed X0: x0h[j2][n] = (fp16 X0[2j2,n], fp16 X0[2j2+1,n])
    for (int i = tid; i < 24 * 256; i += THREADS) {
        int j2 = i >> 8, n = i & 255;
        int b = n >> 4, d = n & 15;
        const float* xb = x + (size_t)(bbase + b) * 624 + d;
        int j0 = 2 * j2, j1 = 2 * j2 + 1;
        float f0 = (j0 < 39) ? xb[j0 * 16] : 0.f;
        float f1 = (j1 < 39) ? xb[j1 * 16] : 0.f;
        x0h[j2 * XR2 + n] = pk16(f0, f1);
    }
    __syncthreads();

    float acc[4][4][4];

    #pragma unroll 1
    for (int l = 0; l < 3; l++) {
        #pragma unroll
        for (int mt = 0; mt < 4; mt++)
            #pragma unroll
            for (int nt = 0; nt < 4; nt++)
                #pragma unroll
                for (int q = 0; q < 4; q++) acc[mt][nt][q] = 0.f;

        const float* bias;
        if (l == 0) {
            bias = b0;
            layer0(w0f, x0h, acc, lane, hg, n_base, grp, tig);
        } else if (l == 1) {
            bias = b1;
            layer12(w1f, xih, x0h, acc, lane, hg, n_base, grp, tig);
        } else {
            bias = b2;
            layer12(w2f, xih, x0h, acc, lane, hg, n_base, grp, tig);
        }

        __syncthreads();   // all warps done reading xih before overwrite

        // ---- register epilogue ----
        int bcol0 = (wid >> 1) * 2;
        #pragma unroll
        for (int mt = 0; mt < 4; mt++) {
            int h0 = h_base + mt * 16 + grp;
            float bv0 = __ldg(bias + h0), bv1 = __ldg(bias + h0 + 8);

            // d-sums (exact fp32)
            #pragma unroll
            for (int half = 0; half < 2; half++) {
                int nt0 = half * 2;
                float s0 = acc[mt][nt0][0] + acc[mt][nt0][1]
                         + acc[mt][nt0 + 1][0] + acc[mt][nt0 + 1][1];
                float s1 = acc[mt][nt0][2] + acc[mt][nt0][3]
                         + acc[mt][nt0 + 1][2] + acc[mt][nt0 + 1][3];
                s0 += __shfl_xor_sync(0xffffffffu, s0, 1);
                s0 += __shfl_xor_sync(0xffffffffu, s0, 2);
                s1 += __shfl_xor_sync(0xffffffffu, s1, 1);
                s1 += __shfl_xor_sync(0xffffffffu, s1, 2);
                if (tig == 0) {
                    size_t ob = (size_t)(bbase + bcol0 + half) * 384 + l * 128;
                    out[ob + h0]     = s0 + 16.f * bv0;
                    out[ob + h0 + 8] = s1 + 16.f * bv1;
                }
            }

            // fp16 Z store for next layer
            if (l < 2) {
                #pragma unroll
                for (int nt = 0; nt < 4; nt++) {
                    int n = n_base + nt * 8 + 2 * tig;
                    float v0 = acc[mt][nt][0] + bv0;
                    float v1 = acc[mt][nt][1] + bv0;
                    float v2 = acc[mt][nt][2] + bv1;
                    float v3 = acc[mt][nt][3] + bv1;
                    float p0 = __shfl_down_sync(0xffffffffu, v0, 4);
                    float p1 = __shfl_down_sync(0xffffffffu, v1, 4);
                    float p2 = __shfl_down_sync(0xffffffffu, v2, 4);
                    float p3 = __shfl_down_sync(0xffffffffu, v3, 4);
                    if (!(grp & 1)) {
                        uint32_t* r0 = xih + (h0 >> 1) * XR2 + n;
                        uint32_t* r1 = xih + ((h0 + 8) >> 1) * XR2 + n;
                        r0[0] = pk16(v0, p0);
                        r0[1] = pk16(v1, p1);
                        r1[0] = pk16(v2, p2);
                        r1[1] = pk16(v3, p3);
                    }
                }
            }
        }
        __syncthreads();   // xih writes visible before next layer reads
    }
}

// -------------------- launch ---------------------------------------------------
extern "C" void kernel_launch(void* const* d_in, const int* in_sizes, int n_in,
                              void* d_out, int out_size) {
    const float* x  = (const float*)d_in[0];
    const float* W0 = (const float*)d_in[1];
    const float* b0 = (const float*)d_in[2];
    const float* W1 = (const float*)d_in[3];
    const float* b1 = (const float*)d_in[4];
    const float* W2 = (const float*)d_in[5];
    const float* b2 = (const float*)d_in[6];
    float* out = (float*)d_out;

    uint4 *w0f, *w1f, *w2f;
    cudaGetSymbolAddress((void**)&w0f, W0f);
    cudaGetSymbolAddress((void**)&w1f, W1f);
    cudaGetSymbolAddress((void**)&w2f, W2f);

    frag_w0<<<(39 * 768 + 255) / 256, 256>>>(W0);
    frag_w<<<(156 * 512 + 255) / 256, 256>>>(W1, w1f);
    frag_w<<<(156 * 512 + 255) / 256, 256>>>(W2, w2f);

    // smem: x0h 24*XR2 + xih 64*XR2 (uint32)
    int smem_bytes = (24 + 64) * XR2 * 4;   // 92,928 B
    cudaFuncSetAttribute(cin_mma, cudaFuncAttributeMaxDynamicSharedMemorySize, smem_bytes);
    cin_mma<<<4096 / NBT, THREADS, smem_bytes>>>(x, w0f, w1f, w2f, b0, b1, b2, out);
}

// round 13
// speedup vs baseline: 1.6373x; 1.6373x over previous
#include <cuda_runtime.h>
#include <cstdint>

// CIN (xDeepFM) via mma.sync m16n8k16 fp16 — round 13.
// L0/L1 as R11 (barrier-free LDG mainloop). Layer 2 replaced by Gram trick:
//   out2[b,h] = sum_c W2[h,c] * G[b,c],  G[b,(j,k)] = sum_d X0[b,j,d]*Z1[b,k,d]
// G built with 48 MMAs/warp from d-pair-packed X0/Z1; final GEMM K=4992 x N=16.

#define THREADS 512
#define NBT     16
#define XR2     264    // u32 row stride for k-pair-packed buffers
#define ZSTR    132    // u32 row stride for d-pair-packed Z1 (aliases xih)
#define GSTR    388    // u32 row stride (per batch) of G chunk

// L0/L1 fragment-ordered fp16 weights: [chunk][k16][hg(2)][mt(4)][lane] uint4
__device__ uint4 W0f[39 * 3 * 2 * 4 * 32];
__device__ uint4 W1f[156 * 2 * 2 * 4 * 32];
// L2 new-order W2 frags: [mt(8)][chunk(8)][j(40)][lane(32)] uint4 (+256 pad)
__device__ uint4 W2g[8 * 8 * 40 * 32 + 256];

__device__ __forceinline__ uint32_t pk16(float lo, float hi) {
    uint32_t r; asm("cvt.rn.f16x2.f32 %0, %1, %2;" : "=r"(r) : "f"(hi), "f"(lo));
    return r;
}
__device__ __forceinline__ uint32_t hmul2(uint32_t a, uint32_t b) {
    uint32_t r; asm("mul.rn.f16x2 %0, %1, %2;" : "=r"(r) : "r"(a), "r"(b));
    return r;
}
__device__ __forceinline__ uint32_t prmt(uint32_t a, uint32_t sel) {
    uint32_t r; asm("prmt.b32 %0, %1, %2, %3;" : "=r"(r) : "r"(a), "r"(a), "r"(sel));
    return r;
}
__device__ __forceinline__ void mma16(float c[4], const uint4 a, uint32_t b0, uint32_t b1) {
    asm volatile(
        "mma.sync.aligned.m16n8k16.row.col.f32.f16.f16.f32 "
        "{%0,%1,%2,%3},{%4,%5,%6,%7},{%8,%9},{%0,%1,%2,%3};"
        : "+f"(c[0]), "+f"(c[1]), "+f"(c[2]), "+f"(c[3])
        : "r"(a.x), "r"(a.y), "r"(a.z), "r"(a.w), "r"(b0), "r"(b1));
}

// -------------------- weight prep ----------------------------------------------
__global__ void frag_w(const float* __restrict__ W, uint4* __restrict__ Wo) {
    int g = blockIdx.x * 256 + threadIdx.x;
    if (g >= 156 * 512) return;
    int lane = g & 31, mt = (g >> 5) & 3, hg = (g >> 7) & 1, ks = (g >> 8) & 1, c = g >> 9;
    int grp = lane >> 2, tig = lane & 3;
    int r0 = (hg * 4 + mt) * 16 + grp, r1 = r0 + 8;
    int kc = c * 32 + ks * 16 + 2 * tig;
    uint4 v;
    v.x = pk16(W[(size_t)r0 * 4992 + kc],     W[(size_t)r0 * 4992 + kc + 1]);
    v.y = pk16(W[(size_t)r1 * 4992 + kc],     W[(size_t)r1 * 4992 + kc + 1]);
    v.z = pk16(W[(size_t)r0 * 4992 + kc + 8], W[(size_t)r0 * 4992 + kc + 9]);
    v.w = pk16(W[(size_t)r1 * 4992 + kc + 8], W[(size_t)r1 * 4992 + kc + 9]);
    Wo[g] = v;
}
__global__ void frag_w0(const float* __restrict__ W) {
    int g = blockIdx.x * 256 + threadIdx.x;
    if (g >= 39 * 768) return;
    int lane = g & 31, mt = (g >> 5) & 3, hg = (g >> 7) & 1;
    int rest = g >> 8;
    int ks = rest % 3, c = rest / 3;
    int grp = lane >> 2, tig = lane & 3;
    int r0 = (hg * 4 + mt) * 16 + grp, r1 = r0 + 8;
    int kp = ks * 16 + 2 * tig;
    const float* w0 = W + (size_t)r0 * 1521 + c * 39;
    const float* w1 = W + (size_t)r1 * 1521 + c * 39;
    auto gv = [&](const float* w, int k) { return (k < 39) ? w[k] : 0.f; };
    uint4 v;
    v.x = pk16(gv(w0, kp),     gv(w0, kp + 1));
    v.y = pk16(gv(w1, kp),     gv(w1, kp + 1));
    v.z = pk16(gv(w0, kp + 8), gv(w0, kp + 9));
    v.w = pk16(gv(w1, kp + 8), gv(w1, kp + 9));
    W0f[g] = v;
}
// W2 in Gram-GEMM order: [mt][chunk][j(40, j=39 pad)][lane]
__global__ void frag_w2g(const float* __restrict__ W) {
    int g = blockIdx.x * 256 + threadIdx.x;
    if (g >= 8 * 8 * 40 * 32) return;
    int lane = g & 31;
    int t = g >> 5;
    int j = t % 40; t /= 40;
    int ch = t & 7, mt = t >> 3;
    int grp = lane >> 2, tig = lane & 3;
    uint4 v = make_uint4(0u, 0u, 0u, 0u);
    if (j < 39) {
        int r0 = mt * 16 + grp, r1 = r0 + 8;
        int c = j * 128 + ch * 16 + 2 * tig;
        v.x = pk16(W[(size_t)r0 * 4992 + c],     W[(size_t)r0 * 4992 + c + 1]);
        v.y = pk16(W[(size_t)r1 * 4992 + c],     W[(size_t)r1 * 4992 + c + 1]);
        v.z = pk16(W[(size_t)r0 * 4992 + c + 8], W[(size_t)r0 * 4992 + c + 9]);
        v.w = pk16(W[(size_t)r1 * 4992 + c + 8], W[(size_t)r1 * 4992 + c + 9]);
    }
    W2g[g] = v;
}

// -------------------- L0/L1 mainloops (as R11) ----------------------------------
__device__ __forceinline__ void layer12(
    const uint4* __restrict__ Wg,
    const uint32_t* xih, const uint32_t* x0h,
    float acc[4][4][4],
    int lane, int hg, int n_base, int grp, int tig)
{
    const uint4* wp = Wg + hg * 128 + lane;
    uint4 A[2][4];
    #pragma unroll
    for (int mt = 0; mt < 4; mt++) A[0][mt] = __ldg(wp + mt * 32);

    #pragma unroll 1
    for (int j = 0; j < 39; j++) {
        uint32_t sel = (j & 1) ? 0x3232u : 0x1010u;
        const uint32_t* x0r = x0h + (j >> 1) * XR2 + n_base + grp;
        uint32_t x0p[4];
        #pragma unroll
        for (int nt = 0; nt < 4; nt++) x0p[nt] = prmt(x0r[nt * 8], sel);

        #pragma unroll
        for (int s = 0; s < 8; s++) {
            int p = s & 1;
            bool last = (j == 38) && (s == 7);
            const uint4* wn = last ? wp : (wp + 256);
            #pragma unroll
            for (int mt = 0; mt < 4; mt++) A[p ^ 1][mt] = __ldg(wn + mt * 32);
            wp = wn;

            const uint32_t* xr = xih + (s * 8 + tig) * XR2 + n_base + grp;
            #pragma unroll
            for (int nt = 0; nt < 4; nt++) {
                uint32_t b0 = hmul2(x0p[nt], xr[nt * 8]);
                uint32_t b1 = hmul2(x0p[nt], xr[4 * XR2 + nt * 8]);
                #pragma unroll
                for (int mt = 0; mt < 4; mt++)
                    mma16(acc[mt][nt], A[p][mt], b0, b1);
            }
        }
    }
}

__device__ __forceinline__ void layer0(
    const uint4* __restrict__ Wg,
    const uint32_t* x0h,
    float acc[4][4][4],
    int lane, int hg, int n_base, int grp, int tig)
{
    const uint4* wp = Wg + hg * 128 + lane;
    #pragma unroll 1
    for (int j = 0; j < 39; j++) {
        uint32_t sel = (j & 1) ? 0x3232u : 0x1010u;
        const uint32_t* x0r = x0h + (j >> 1) * XR2 + n_base + grp;
        uint32_t x0p[4];
        #pragma unroll
        for (int nt = 0; nt < 4; nt++) x0p[nt] = prmt(x0r[nt * 8], sel);

        #pragma unroll
        for (int ks = 0; ks < 3; ks++) {
            uint4 A[4];
            #pragma unroll
            for (int mt = 0; mt < 4; mt++) A[mt] = __ldg(wp + mt * 32);
            wp += 256;
            const uint32_t* xr = x0h + (ks * 8 + tig) * XR2 + n_base + grp;
            #pragma unroll
            for (int nt = 0; nt < 4; nt++) {
                uint32_t b0 = hmul2(x0p[nt], xr[nt * 8]);
                uint32_t b1 = hmul2(x0p[nt], xr[4 * XR2 + nt * 8]);
                #pragma unroll
                for (int mt = 0; mt < 4; mt++)
                    mma16(acc[mt][nt], A[mt], b0, b1);
            }
        }
    }
}

// -------------------- main fused kernel -----------------------------------------
__global__ void __launch_bounds__(THREADS)
cin_mma(const float* __restrict__ x,
        const uint4* __restrict__ w0f, const uint4* __restrict__ w1f,
        const uint4* __restrict__ w2g,
        const float* __restrict__ b0, const float* __restrict__ b1,
        const float* __restrict__ b2,
        float* __restrict__ out)
{
    extern __shared__ uint32_t smu[];
    uint32_t* x0h = smu;                       // 24 pair-rows x XR2
    uint32_t* xih = smu + 24 * XR2;            // 64 x XR2  (aliased as z1d 128 x ZSTR)
    uint32_t* z1d = xih;
    uint4*    x0d = (uint4*)(smu + 88 * XR2);            // 16 b x 3 jt x 32 lanes
    uint32_t* g2s = smu + 88 * XR2 + 16 * 96 * 4;        // 16 b x GSTR

    int tid = threadIdx.x;
    int lane = tid & 31, wid = tid >> 5;
    int grp = lane >> 2, tig = lane & 3;
    int hg = wid & 1;
    int h_base = hg * 64, n_base = (wid >> 1) * 32;
    int bbase = blockIdx.x * NBT;

    // build k-pair-packed X0
    for (int i = tid; i < 24 * 256; i += THREADS) {
        int j2 = i >> 8, n = i & 255;
        int b = n >> 4, d = n & 15;
        const float* xb = x + (size_t)(bbase + b) * 624 + d;
        int j0 = 2 * j2, j1 = 2 * j2 + 1;
        float f0 = (j0 < 39) ? xb[j0 * 16] : 0.f;
        float f1 = (j1 < 39) ? xb[j1 * 16] : 0.f;
        x0h[j2 * XR2 + n] = pk16(f0, f1);
    }
    // build d-pair-packed X0 A-frags (warp = batch)
    {
        const float* xb = x + (size_t)(bbase + wid) * 624;
        #pragma unroll
        for (int jt = 0; jt < 3; jt++) {
            int j0 = jt * 16 + grp, j1 = j0 + 8;
            float2 z2 = make_float2(0.f, 0.f);
            float2 a0 = (j0 < 39) ? *(const float2*)(xb + j0 * 16 + 2 * tig)     : z2;
            float2 a1 = (j0 < 39) ? *(const float2*)(xb + j0 * 16 + 2 * tig + 8) : z2;
            float2 c0 = (j1 < 39) ? *(const float2*)(xb + j1 * 16 + 2 * tig)     : z2;
            float2 c1 = (j1 < 39) ? *(const float2*)(xb + j1 * 16 + 2 * tig + 8) : z2;
            uint4 v;
            v.x = pk16(a0.x, a0.y);
            v.y = pk16(c0.x, c0.y);
            v.z = pk16(a1.x, a1.y);
            v.w = pk16(c1.x, c1.y);
            x0d[(wid * 3 + jt) * 32 + lane] = v;
        }
    }
    __syncthreads();

    float acc[4][4][4];
    int bcol0 = (wid >> 1) * 2;

    // ================= layers 0 and 1 =================
    #pragma unroll 1
    for (int l = 0; l < 2; l++) {
        #pragma unroll
        for (int mt = 0; mt < 4; mt++)
            #pragma unroll
            for (int nt = 0; nt < 4; nt++)
                #pragma unroll
                for (int q = 0; q < 4; q++) acc[mt][nt][q] = 0.f;

        const float* bias;
        if (l == 0) {
            bias = b0;
            layer0(w0f, x0h, acc, lane, hg, n_base, grp, tig);
        } else {
            bias = b1;
            layer12(w1f, xih, x0h, acc, lane, hg, n_base, grp, tig);
        }
        __syncthreads();   // all reads of xih done before overwrite

        #pragma unroll
        for (int mt = 0; mt < 4; mt++) {
            int h0 = h_base + mt * 16 + grp;
            float bv0 = __ldg(bias + h0), bv1 = __ldg(bias + h0 + 8);

            // d-sums
            #pragma unroll
            for (int half = 0; half < 2; half++) {
                int nt0 = half * 2;
                float s0 = acc[mt][nt0][0] + acc[mt][nt0][1]
                         + acc[mt][nt0 + 1][0] + acc[mt][nt0 + 1][1];
                float s1 = acc[mt][nt0][2] + acc[mt][nt0][3]
                         + acc[mt][nt0 + 1][2] + acc[mt][nt0 + 1][3];
                s0 += __shfl_xor_sync(0xffffffffu, s0, 1);
                s0 += __shfl_xor_sync(0xffffffffu, s0, 2);
                s1 += __shfl_xor_sync(0xffffffffu, s1, 1);
                s1 += __shfl_xor_sync(0xffffffffu, s1, 2);
                if (tig == 0) {
                    size_t ob = (size_t)(bbase + bcol0 + half) * 384 + l * 128;
                    out[ob + h0]     = s0 + 16.f * bv0;
                    out[ob + h0 + 8] = s1 + 16.f * bv1;
                }
            }

            if (l == 0) {
                // k-pair-packed Z0 -> xih (shfl pairing, as R11)
                #pragma unroll
                for (int nt = 0; nt < 4; nt++) {
                    int n = n_base + nt * 8 + 2 * tig;
                    float v0 = acc[mt][nt][0] + bv0;
                    float v1 = acc[mt][nt][1] + bv0;
                    float v2 = acc[mt][nt][2] + bv1;
                    float v3 = acc[mt][nt][3] + bv1;
                    float p0 = __shfl_down_sync(0xffffffffu, v0, 4);
                    float p1 = __shfl_down_sync(0xffffffffu, v1, 4);
                    float p2 = __shfl_down_sync(0xffffffffu, v2, 4);
                    float p3 = __shfl_down_sync(0xffffffffu, v3, 4);
                    if (!(grp & 1)) {
                        uint32_t* r0 = xih + (h0 >> 1) * XR2 + n;
                        uint32_t* r1 = xih + ((h0 + 8) >> 1) * XR2 + n;
                        r0[0] = pk16(v0, p0);
                        r0[1] = pk16(v1, p1);
                        r1[0] = pk16(v2, p2);
                        r1[1] = pk16(v3, p3);
                    }
                }
            } else {
                // d-pair-packed Z1 -> z1d (no shuffles; v0/v1 are a d-pair)
                #pragma unroll
                for (int nt = 0; nt < 4; nt++) {
                    int n = n_base + nt * 8 + 2 * tig;
                    int col = (n >> 4) * 8 + ((n >> 1) & 7);
                    z1d[h0 * ZSTR + col]       = pk16(acc[mt][nt][0] + bv0,
                                                      acc[mt][nt][1] + bv0);
                    z1d[(h0 + 8) * ZSTR + col] = pk16(acc[mt][nt][2] + bv1,
                                                      acc[mt][nt][3] + bv1);
                }
            }
        }
        __syncthreads();
    }

    // ================= layer 2 via Gram trick =================
    int mtw = wid & 7, ntw = wid >> 3;
    float fA[4] = {0.f, 0.f, 0.f, 0.f};
    float fB[4] = {0.f, 0.f, 0.f, 0.f};

    const uint4* wp2 = w2g + (size_t)(mtw * 8) * 40 * 32 + lane;
    uint4 R[8];
    #pragma unroll
    for (int r = 0; r < 8; r++) R[r] = __ldg(wp2 + r * 32);
    wp2 += 8 * 32;

    #pragma unroll 1
    for (int ch = 0; ch < 8; ch++) {
        // ---- G-MMA: warp = batch wid; G[j, 16 k of this chunk] ----
        #pragma unroll
        for (int jt = 0; jt < 3; jt++) {
            uint4 A = x0d[(wid * 3 + jt) * 32 + lane];
            #pragma unroll
            for (int ks = 0; ks < 2; ks++) {
                int kk = ch * 16 + ks * 8 + grp;
                uint32_t bb0 = z1d[kk * ZSTR + wid * 8 + tig];
                uint32_t bb1 = z1d[kk * ZSTR + wid * 8 + tig + 4];
                float g4[4] = {0.f, 0.f, 0.f, 0.f};
                mma16(g4, A, bb0, bb1);
                int c2l = (jt * 16 + grp) * 8 + ks * 4 + tig;
                g2s[wid * GSTR + c2l]      = pk16(g4[0], g4[1]);
                g2s[wid * GSTR + c2l + 64] = pk16(g4[2], g4[3]);
            }
        }
        __syncthreads();

        // ---- final GEMM: 40 ksteps (j=39 contributes zero) ----
        const uint32_t* gb = g2s + (ntw * 8 + grp) * GSTR + tig;
        #pragma unroll
        for (int j = 0; j < 40; j++) {
            uint4 A = R[j & 7];
            R[j & 7] = __ldg(wp2);
            wp2 += 32;
            uint32_t bb0 = gb[j * 8];
            uint32_t bb1 = gb[j * 8 + 4];
            if (j & 1) mma16(fB, A, bb0, bb1);
            else       mma16(fA, A, bb0, bb1);
        }
        __syncthreads();
    }

    // out2 epilogue
    {
        int h0 = mtw * 16 + grp;
        float bv0 = 16.f * __ldg(b2 + h0);
        float bv1 = 16.f * __ldg(b2 + h0 + 8);
        int bq = ntw * 8 + 2 * tig;
        size_t ob = (size_t)(bbase + bq) * 384 + 256;
        out[ob + h0]           = fA[0] + fB[0] + bv0;
        out[ob + 384 + h0]     = fA[1] + fB[1] + bv0;
        out[ob + h0 + 8]       = fA[2] + fB[2] + bv1;
        out[ob + 384 + h0 + 8] = fA[3] + fB[3] + bv1;
    }
}

// -------------------- launch -------------------------------------------------------
extern "C" void kernel_launch(void* const* d_in, const int* in_sizes, int n_in,
                              void* d_out, int out_size) {
    const float* x  = (const float*)d_in[0];
    const float* W0 = (const float*)d_in[1];
    const float* b0 = (const float*)d_in[2];
    const float* W1 = (const float*)d_in[3];
    const float* b1 = (const float*)d_in[4];
    const float* W2 = (const float*)d_in[5];
    const float* b2 = (const float*)d_in[6];
    float* out = (float*)d_out;

    uint4 *w0f, *w1f, *w2g;
    cudaGetSymbolAddress((void**)&w0f, W0f);
    cudaGetSymbolAddress((void**)&w1f, W1f);
    cudaGetSymbolAddress((void**)&w2g, W2g);

    frag_w0<<<(39 * 768 + 255) / 256, 256>>>(W0);
    frag_w<<<(156 * 512 + 255) / 256, 256>>>(W1, w1f);
    frag_w2g<<<(8 * 8 * 40 * 32 + 255) / 256, 256>>>(W2);

    // smem: x0h 24*XR2 + xih/z1d 64*XR2 + x0d 6144 + g2s 16*GSTR (u32)
    int smem_u32 = 88 * XR2 + 16 * 96 * 4 + 16 * GSTR;
    int smem_bytes = smem_u32 * 4;   // 142,336 B
    cudaFuncSetAttribute(cin_mma, cudaFuncAttributeMaxDynamicSharedMemorySize, smem_bytes);
    cin_mma<<<4096 / NBT, THREADS, smem_bytes>>>(x, w0f, w1f, w2g, b0, b1, b2, out);
}

// round 14
// speedup vs baseline: 1.6508x; 1.0083x over previous
#include <cuda_runtime.h>
#include <cstdint>

// CIN (xDeepFM) via mma.sync m16n8k16 fp16 — round 14.
// R13 Gram-trick kernel at NBT=8 / 256 threads / 2 CTAs per SM.
// L0/L1 barrier-free LDG mainloops; L2 via G[b,j,k]=sum_d X0*Z1 + small GEMM.

#define THREADS 256
#define NBT     8
#define XR2     136    // u32 row stride, k-pair-packed buffers (mod 32 == 8)
#define ZSTR    68     // u32 row stride, d-pair-packed Z1 (aliases xih)
#define GSTR    388    // u32 row stride (per batch) of G chunk

// L0/L1 fragment-ordered fp16 weights: [chunk][k16][hg(2)][mt(4)][lane] uint4
__device__ uint4 W0f[39 * 3 * 2 * 4 * 32];
__device__ uint4 W1f[156 * 2 * 2 * 4 * 32];
// L2 Gram-order W2 frags: [mt(8)][chunk(8)][j(40)][lane(32)] uint4 (+256 pad)
__device__ uint4 W2g[8 * 8 * 40 * 32 + 256];

__device__ __forceinline__ uint32_t pk16(float lo, float hi) {
    uint32_t r; asm("cvt.rn.f16x2.f32 %0, %1, %2;" : "=r"(r) : "f"(hi), "f"(lo));
    return r;
}
__device__ __forceinline__ uint32_t hmul2(uint32_t a, uint32_t b) {
    uint32_t r; asm("mul.rn.f16x2 %0, %1, %2;" : "=r"(r) : "r"(a), "r"(b));
    return r;
}
__device__ __forceinline__ uint32_t prmt(uint32_t a, uint32_t sel) {
    uint32_t r; asm("prmt.b32 %0, %1, %2, %3;" : "=r"(r) : "r"(a), "r"(a), "r"(sel));
    return r;
}
__device__ __forceinline__ void mma16(float c[4], const uint4 a, uint32_t b0, uint32_t b1) {
    asm volatile(
        "mma.sync.aligned.m16n8k16.row.col.f32.f16.f16.f32 "
        "{%0,%1,%2,%3},{%4,%5,%6,%7},{%8,%9},{%0,%1,%2,%3};"
        : "+f"(c[0]), "+f"(c[1]), "+f"(c[2]), "+f"(c[3])
        : "r"(a.x), "r"(a.y), "r"(a.z), "r"(a.w), "r"(b0), "r"(b1));
}

// -------------------- weight prep (same as R13) ----------------------------------
__global__ void frag_w(const float* __restrict__ W, uint4* __restrict__ Wo) {
    int g = blockIdx.x * 256 + threadIdx.x;
    if (g >= 156 * 512) return;
    int lane = g & 31, mt = (g >> 5) & 3, hg = (g >> 7) & 1, ks = (g >> 8) & 1, c = g >> 9;
    int grp = lane >> 2, tig = lane & 3;
    int r0 = (hg * 4 + mt) * 16 + grp, r1 = r0 + 8;
    int kc = c * 32 + ks * 16 + 2 * tig;
    uint4 v;
    v.x = pk16(W[(size_t)r0 * 4992 + kc],     W[(size_t)r0 * 4992 + kc + 1]);
    v.y = pk16(W[(size_t)r1 * 4992 + kc],     W[(size_t)r1 * 4992 + kc + 1]);
    v.z = pk16(W[(size_t)r0 * 4992 + kc + 8], W[(size_t)r0 * 4992 + kc + 9]);
    v.w = pk16(W[(size_t)r1 * 4992 + kc + 8], W[(size_t)r1 * 4992 + kc + 9]);
    Wo[g] = v;
}
__global__ void frag_w0(const float* __restrict__ W) {
    int g = blockIdx.x * 256 + threadIdx.x;
    if (g >= 39 * 768) return;
    int lane = g & 31, mt = (g >> 5) & 3, hg = (g >> 7) & 1;
    int rest = g >> 8;
    int ks = rest % 3, c = rest / 3;
    int grp = lane >> 2, tig = lane & 3;
    int r0 = (hg * 4 + mt) * 16 + grp, r1 = r0 + 8;
    int kp = ks * 16 + 2 * tig;
    const float* w0 = W + (size_t)r0 * 1521 + c * 39;
    const float* w1 = W + (size_t)r1 * 1521 + c * 39;
    auto gv = [&](const float* w, int k) { return (k < 39) ? w[k] : 0.f; };
    uint4 v;
    v.x = pk16(gv(w0, kp),     gv(w0, kp + 1));
    v.y = pk16(gv(w1, kp),     gv(w1, kp + 1));
    v.z = pk16(gv(w0, kp + 8), gv(w0, kp + 9));
    v.w = pk16(gv(w1, kp + 8), gv(w1, kp + 9));
    W0f[g] = v;
}
__global__ void frag_w2g(const float* __restrict__ W) {
    int g = blockIdx.x * 256 + threadIdx.x;
    if (g >= 8 * 8 * 40 * 32) return;
    int lane = g & 31;
    int t = g >> 5;
    int j = t % 40; t /= 40;
    int ch = t & 7, mt = t >> 3;
    int grp = lane >> 2, tig = lane & 3;
    uint4 v = make_uint4(0u, 0u, 0u, 0u);
    if (j < 39) {
        int r0 = mt * 16 + grp, r1 = r0 + 8;
        int c = j * 128 + ch * 16 + 2 * tig;
        v.x = pk16(W[(size_t)r0 * 4992 + c],     W[(size_t)r0 * 4992 + c + 1]);
        v.y = pk16(W[(size_t)r1 * 4992 + c],     W[(size_t)r1 * 4992 + c + 1]);
        v.z = pk16(W[(size_t)r0 * 4992 + c + 8], W[(size_t)r0 * 4992 + c + 9]);
        v.w = pk16(W[(size_t)r1 * 4992 + c + 8], W[(size_t)r1 * 4992 + c + 9]);
    }
    W2g[g] = v;
}

// -------------------- L0/L1 mainloops ---------------------------------------------
__device__ __forceinline__ void layer12(
    const uint4* __restrict__ Wg,
    const uint32_t* xih, const uint32_t* x0h,
    float acc[4][4][4],
    int lane, int hg, int n_base, int grp, int tig)
{
    const uint4* wp = Wg + hg * 128 + lane;
    uint4 A[2][4];
    #pragma unroll
    for (int mt = 0; mt < 4; mt++) A[0][mt] = __ldg(wp + mt * 32);

    #pragma unroll 1
    for (int j = 0; j < 39; j++) {
        uint32_t sel = (j & 1) ? 0x3232u : 0x1010u;
        const uint32_t* x0r = x0h + (j >> 1) * XR2 + n_base + grp;
        uint32_t x0p[4];
        #pragma unroll
        for (int nt = 0; nt < 4; nt++) x0p[nt] = prmt(x0r[nt * 8], sel);

        #pragma unroll
        for (int s = 0; s < 8; s++) {
            int p = s & 1;
            bool last = (j == 38) && (s == 7);
            const uint4* wn = last ? wp : (wp + 256);
            #pragma unroll
            for (int mt = 0; mt < 4; mt++) A[p ^ 1][mt] = __ldg(wn + mt * 32);
            wp = wn;

            const uint32_t* xr = xih + (s * 8 + tig) * XR2 + n_base + grp;
            #pragma unroll
            for (int nt = 0; nt < 4; nt++) {
                uint32_t b0 = hmul2(x0p[nt], xr[nt * 8]);
                uint32_t b1 = hmul2(x0p[nt], xr[4 * XR2 + nt * 8]);
                #pragma unroll
                for (int mt = 0; mt < 4; mt++)
                    mma16(acc[mt][nt], A[p][mt], b0, b1);
            }
        }
    }
}

__device__ __forceinline__ void layer0(
    const uint4* __restrict__ Wg,
    const uint32_t* x0h,
    float acc[4][4][4],
    int lane, int hg, int n_base, int grp, int tig)
{
    const uint4* wp = Wg + hg * 128 + lane;
    #pragma unroll 1
    for (int j = 0; j < 39; j++) {
        uint32_t sel = (j & 1) ? 0x3232u : 0x1010u;
        const uint32_t* x0r = x0h + (j >> 1) * XR2 + n_base + grp;
        uint32_t x0p[4];
        #pragma unroll
        for (int nt = 0; nt < 4; nt++) x0p[nt] = prmt(x0r[nt * 8], sel);

        #pragma unroll
        for (int ks = 0; ks < 3; ks++) {
            uint4 A[4];
            #pragma unroll
            for (int mt = 0; mt < 4; mt++) A[mt] = __ldg(wp + mt * 32);
            wp += 256;
            const uint32_t* xr = x0h + (ks * 8 + tig) * XR2 + n_base + grp;
            #pragma unroll
            for (int nt = 0; nt < 4; nt++) {
                uint32_t b0 = hmul2(x0p[nt], xr[nt * 8]);
                uint32_t b1 = hmul2(x0p[nt], xr[4 * XR2 + nt * 8]);
                #pragma unroll
                for (int mt = 0; mt < 4; mt++)
                    mma16(acc[mt][nt], A[mt], b0, b1);
            }
        }
    }
}

// -------------------- main fused kernel --------------------------------------------
__global__ void __launch_bounds__(THREADS, 2)
cin_mma(const float* __restrict__ x,
        const uint4* __restrict__ w0f, const uint4* __restrict__ w1f,
        const uint4* __restrict__ w2g,
        const float* __restrict__ b0, const float* __restrict__ b1,
        const float* __restrict__ b2,
        float* __restrict__ out)
{
    extern __shared__ uint32_t smu[];
    uint32_t* x0h = smu;                       // 24 pair-rows x XR2
    uint32_t* xih = smu + 24 * XR2;            // 64 x XR2 (aliased as z1d 128 x ZSTR)
    uint32_t* z1d = xih;
    uint4*    x0d = (uint4*)(smu + 88 * XR2);            // 8 b x 3 jt x 32 lanes
    uint32_t* g2s = smu + 88 * XR2 + 8 * 96 * 4;         // 8 b x GSTR

    int tid = threadIdx.x;
    int lane = tid & 31, wid = tid >> 5;
    int grp = lane >> 2, tig = lane & 3;
    int hg = wid & 1;
    int h_base = hg * 64, n_base = (wid >> 1) * 32;
    int bbase = blockIdx.x * NBT;

    // k-pair-packed X0
    for (int i = tid; i < 24 * 128; i += THREADS) {
        int j2 = i >> 7, n = i & 127;
        int b = n >> 4, d = n & 15;
        const float* xb = x + (size_t)(bbase + b) * 624 + d;
        int j0 = 2 * j2, j1 = 2 * j2 + 1;
        float f0 = (j0 < 39) ? xb[j0 * 16] : 0.f;
        float f1 = (j1 < 39) ? xb[j1 * 16] : 0.f;
        x0h[j2 * XR2 + n] = pk16(f0, f1);
    }
    // d-pair-packed X0 A-frags (warp = batch)
    {
        const float* xb = x + (size_t)(bbase + wid) * 624;
        #pragma unroll
        for (int jt = 0; jt < 3; jt++) {
            int j0 = jt * 16 + grp, j1 = j0 + 8;
            float2 z2 = make_float2(0.f, 0.f);
            float2 a0 = (j0 < 39) ? *(const float2*)(xb + j0 * 16 + 2 * tig)     : z2;
            float2 a1 = (j0 < 39) ? *(const float2*)(xb + j0 * 16 + 2 * tig + 8) : z2;
            float2 c0 = (j1 < 39) ? *(const float2*)(xb + j1 * 16 + 2 * tig)     : z2;
            float2 c1 = (j1 < 39) ? *(const float2*)(xb + j1 * 16 + 2 * tig + 8) : z2;
            uint4 v;
            v.x = pk16(a0.x, a0.y);
            v.y = pk16(c0.x, c0.y);
            v.z = pk16(a1.x, a1.y);
            v.w = pk16(c1.x, c1.y);
            x0d[(wid * 3 + jt) * 32 + lane] = v;
        }
    }
    __syncthreads();

    float acc[4][4][4];
    int bcol0 = (wid >> 1) * 2;

    // ================= layers 0 and 1 =================
    #pragma unroll 1
    for (int l = 0; l < 2; l++) {
        #pragma unroll
        for (int mt = 0; mt < 4; mt++)
            #pragma unroll
            for (int nt = 0; nt < 4; nt++)
                #pragma unroll
                for (int q = 0; q < 4; q++) acc[mt][nt][q] = 0.f;

        const float* bias;
        if (l == 0) {
            bias = b0;
            layer0(w0f, x0h, acc, lane, hg, n_base, grp, tig);
        } else {
            bias = b1;
            layer12(w1f, xih, x0h, acc, lane, hg, n_base, grp, tig);
        }
        __syncthreads();   // all reads of xih done before overwrite

        #pragma unroll
        for (int mt = 0; mt < 4; mt++) {
            int h0 = h_base + mt * 16 + grp;
            float bv0 = __ldg(bias + h0), bv1 = __ldg(bias + h0 + 8);

            // d-sums
            #pragma unroll
            for (int half = 0; half < 2; half++) {
                int nt0 = half * 2;
                float s0 = acc[mt][nt0][0] + acc[mt][nt0][1]
                         + acc[mt][nt0 + 1][0] + acc[mt][nt0 + 1][1];
                float s1 = acc[mt][nt0][2] + acc[mt][nt0][3]
                         + acc[mt][nt0 + 1][2] + acc[mt][nt0 + 1][3];
                s0 += __shfl_xor_sync(0xffffffffu, s0, 1);
                s0 += __shfl_xor_sync(0xffffffffu, s0, 2);
                s1 += __shfl_xor_sync(0xffffffffu, s1, 1);
                s1 += __shfl_xor_sync(0xffffffffu, s1, 2);
                if (tig == 0) {
                    size_t ob = (size_t)(bbase + bcol0 + half) * 384 + l * 128;
                    out[ob + h0]     = s0 + 16.f * bv0;
                    out[ob + h0 + 8] = s1 + 16.f * bv1;
                }
            }

            if (l == 0) {
                // k-pair-packed Z0 -> xih
                #pragma unroll
                for (int nt = 0; nt < 4; nt++) {
                    int n = n_base + nt * 8 + 2 * tig;
                    float v0 = acc[mt][nt][0] + bv0;
                    float v1 = acc[mt][nt][1] + bv0;
                    float v2 = acc[mt][nt][2] + bv1;
                    float v3 = acc[mt][nt][3] + bv1;
                    float p0 = __shfl_down_sync(0xffffffffu, v0, 4);
                    float p1 = __shfl_down_sync(0xffffffffu, v1, 4);
                    float p2 = __shfl_down_sync(0xffffffffu, v2, 4);
                    float p3 = __shfl_down_sync(0xffffffffu, v3, 4);
                    if (!(grp & 1)) {
                        uint32_t* r0 = xih + (h0 >> 1) * XR2 + n;
                        uint32_t* r1 = xih + ((h0 + 8) >> 1) * XR2 + n;
                        r0[0] = pk16(v0, p0);
                        r0[1] = pk16(v1, p1);
                        r1[0] = pk16(v2, p2);
                        r1[1] = pk16(v3, p3);
                    }
                }
            } else {
                // d-pair-packed Z1 -> z1d
                #pragma unroll
                for (int nt = 0; nt < 4; nt++) {
                    int n = n_base + nt * 8 + 2 * tig;
                    int col = (n >> 4) * 8 + ((n >> 1) & 7);
                    z1d[h0 * ZSTR + col]       = pk16(acc[mt][nt][0] + bv0,
                                                      acc[mt][nt][1] + bv0);
                    z1d[(h0 + 8) * ZSTR + col] = pk16(acc[mt][nt][2] + bv1,
                                                      acc[mt][nt][3] + bv1);
                }
            }
        }
        __syncthreads();
    }

    // ================= layer 2 via Gram trick =================
    int mtw = wid;                      // 8 warps = 8 m-tiles; all batches per warp
    float fA[4] = {0.f, 0.f, 0.f, 0.f};
    float fB[4] = {0.f, 0.f, 0.f, 0.f};

    const uint4* wp2 = w2g + (size_t)(mtw * 8) * 40 * 32 + lane;
    uint4 R[8];
    #pragma unroll
    for (int r = 0; r < 8; r++) R[r] = __ldg(wp2 + r * 32);
    wp2 += 8 * 32;

    #pragma unroll 1
    for (int ch = 0; ch < 8; ch++) {
        // G-MMA: warp = batch wid
        #pragma unroll
        for (int jt = 0; jt < 3; jt++) {
            uint4 A = x0d[(wid * 3 + jt) * 32 + lane];
            #pragma unroll
            for (int ks = 0; ks < 2; ks++) {
                int kk = ch * 16 + ks * 8 + grp;
                uint32_t bb0 = z1d[kk * ZSTR + wid * 8 + tig];
                uint32_t bb1 = z1d[kk * ZSTR + wid * 8 + tig + 4];
                float g4[4] = {0.f, 0.f, 0.f, 0.f};
                mma16(g4, A, bb0, bb1);
                int c2l = (jt * 16 + grp) * 8 + ks * 4 + tig;
                g2s[wid * GSTR + c2l]      = pk16(g4[0], g4[1]);
                g2s[wid * GSTR + c2l + 64] = pk16(g4[2], g4[3]);
            }
        }
        __syncthreads();

        // final GEMM: 40 ksteps (j=39 zero)
        const uint32_t* gb = g2s + grp * GSTR + tig;
        #pragma unroll
        for (int j = 0; j < 40; j++) {
            uint4 A = R[j & 7];
            R[j & 7] = __ldg(wp2);
            wp2 += 32;
            uint32_t bb0 = gb[j * 8];
            uint32_t bb1 = gb[j * 8 + 4];
            if (j & 1) mma16(fB, A, bb0, bb1);
            else       mma16(fA, A, bb0, bb1);
        }
        __syncthreads();
    }

    // out2 epilogue
    {
        int h0 = mtw * 16 + grp;
        float bv0 = 16.f * __ldg(b2 + h0);
        float bv1 = 16.f * __ldg(b2 + h0 + 8);
        int bq = 2 * tig;
        size_t ob = (size_t)(bbase + bq) * 384 + 256;
        out[ob + h0]           = fA[0] + fB[0] + bv0;
        out[ob + 384 + h0]     = fA[1] + fB[1] + bv0;
        out[ob + h0 + 8]       = fA[2] + fB[2] + bv1;
        out[ob + 384 + h0 + 8] = fA[3] + fB[3] + bv1;
    }
}

// -------------------- launch ----------------------------------------------------------
extern "C" void kernel_launch(void* const* d_in, const int* in_sizes, int n_in,
                              void* d_out, int out_size) {
    const float* x  = (const float*)d_in[0];
    const float* W0 = (const float*)d_in[1];
    const float* b0 = (const float*)d_in[2];
    const float* W1 = (const float*)d_in[3];
    const float* b1 = (const float*)d_in[4];
    const float* W2 = (const float*)d_in[5];
    const float* b2 = (const float*)d_in[6];
    float* out = (float*)d_out;

    uint4 *w0f, *w1f, *w2g;
    cudaGetSymbolAddress((void**)&w0f, W0f);
    cudaGetSymbolAddress((void**)&w1f, W1f);
    cudaGetSymbolAddress((void**)&w2g, W2g);

    frag_w0<<<(39 * 768 + 255) / 256, 256>>>(W0);
    frag_w<<<(156 * 512 + 255) / 256, 256>>>(W1, w1f);
    frag_w2g<<<(8 * 8 * 40 * 32 + 255) / 256, 256>>>(W2);

    // smem: x0h 24*XR2 + xih/z1d 64*XR2 + x0d 3072 + g2s 8*GSTR  (u32)
    int smem_u32 = 88 * XR2 + 8 * 96 * 4 + 8 * GSTR;
    int smem_bytes = smem_u32 * 4;   // 72,576 B  -> 2 CTAs/SM
    cudaFuncSetAttribute(cin_mma, cudaFuncAttributeMaxDynamicSharedMemorySize, smem_bytes);
    cin_mma<<<4096 / NBT, THREADS, smem_bytes>>>(x, w0f, w1f, w2g, b0, b1, b2, out);
}

// round 15
// speedup vs baseline: 1.7020x; 1.0310x over previous
#include <cuda_runtime.h>
#include <cstdint>

// CIN (xDeepFM) via mma.sync m16n8k16 fp16 — round 15.
// Loop-interchanged L0/L1 mainloops: s (k-slice) outer with Xi slice held in
// registers; j inner sweeping W frags [s][j][hg][mt][lane] via LDG double-buffer.
// L2 via Gram trick (R13). NBT=8, 256 thr, 2 CTAs/SM.

#define THREADS 256
#define NBT     8
#define XR2     136    // u32 row stride, k-pair-packed buffers (mod 32 == 8)
#define ZSTR    68     // u32 row stride, d-pair-packed Z1 (aliases xih)
#define GSTR    388    // u32 row stride (per batch) of G chunk

// L0/L1 fp16 weight frags, s-major: [s][j(39)][hg(2)][mt(4)][lane(32)] uint4 (+256 pad)
__device__ uint4 W0f[3 * 39 * 256 + 256];
__device__ uint4 W1f[8 * 39 * 256 + 256];
// L2 Gram-order W2 frags: [mt(8)][chunk(8)][j(40)][lane(32)] uint4 (+256 pad)
__device__ uint4 W2g[8 * 8 * 40 * 32 + 256];

__device__ __forceinline__ uint32_t pk16(float lo, float hi) {
    uint32_t r; asm("cvt.rn.f16x2.f32 %0, %1, %2;" : "=r"(r) : "f"(hi), "f"(lo));
    return r;
}
__device__ __forceinline__ uint32_t hmul2(uint32_t a, uint32_t b) {
    uint32_t r; asm("mul.rn.f16x2 %0, %1, %2;" : "=r"(r) : "r"(a), "r"(b));
    return r;
}
__device__ __forceinline__ uint32_t prmt(uint32_t a, uint32_t sel) {
    uint32_t r; asm("prmt.b32 %0, %1, %2, %3;" : "=r"(r) : "r"(a), "r"(a), "r"(sel));
    return r;
}
__device__ __forceinline__ void mma16(float c[4], const uint4 a, uint32_t b0, uint32_t b1) {
    asm volatile(
        "mma.sync.aligned.m16n8k16.row.col.f32.f16.f16.f32 "
        "{%0,%1,%2,%3},{%4,%5,%6,%7},{%8,%9},{%0,%1,%2,%3};"
        : "+f"(c[0]), "+f"(c[1]), "+f"(c[2]), "+f"(c[3])
        : "r"(a.x), "r"(a.y), "r"(a.z), "r"(a.w), "r"(b0), "r"(b1));
}

// -------------------- weight prep -------------------------------------------------
// W1: [s(8)][j(39)][hg][mt][lane], k = j*128 + s*16 + frag offset
__global__ void frag_w1(const float* __restrict__ W, uint4* __restrict__ Wo) {
    int g = blockIdx.x * 256 + threadIdx.x;
    if (g >= 8 * 39 * 256) return;
    int lane = g & 31, mt = (g >> 5) & 3, hg = (g >> 7) & 1;
    int t = g >> 8;
    int j = t % 39, s = t / 39;
    int grp = lane >> 2, tig = lane & 3;
    int r0 = (hg * 4 + mt) * 16 + grp, r1 = r0 + 8;
    int k = j * 128 + s * 16 + 2 * tig;
    uint4 v;
    v.x = pk16(W[(size_t)r0 * 4992 + k],     W[(size_t)r0 * 4992 + k + 1]);
    v.y = pk16(W[(size_t)r1 * 4992 + k],     W[(size_t)r1 * 4992 + k + 1]);
    v.z = pk16(W[(size_t)r0 * 4992 + k + 8], W[(size_t)r0 * 4992 + k + 9]);
    v.w = pk16(W[(size_t)r1 * 4992 + k + 8], W[(size_t)r1 * 4992 + k + 9]);
    Wo[g] = v;
}
// W0: [s(3)][j(39)][hg][mt][lane], k = j*39 + kl, kl >= 39 -> 0
__global__ void frag_w0(const float* __restrict__ W) {
    int g = blockIdx.x * 256 + threadIdx.x;
    if (g >= 3 * 39 * 256) return;
    int lane = g & 31, mt = (g >> 5) & 3, hg = (g >> 7) & 1;
    int t = g >> 8;
    int j = t % 39, s = t / 39;
    int grp = lane >> 2, tig = lane & 3;
    int r0 = (hg * 4 + mt) * 16 + grp, r1 = r0 + 8;
    int kl = s * 16 + 2 * tig;
    const float* w0 = W + (size_t)r0 * 1521 + j * 39;
    const float* w1 = W + (size_t)r1 * 1521 + j * 39;
    auto gv = [&](const float* w, int kk) { return (kk < 39) ? w[kk] : 0.f; };
    uint4 v;
    v.x = pk16(gv(w0, kl),     gv(w0, kl + 1));
    v.y = pk16(gv(w1, kl),     gv(w1, kl + 1));
    v.z = pk16(gv(w0, kl + 8), gv(w0, kl + 9));
    v.w = pk16(gv(w1, kl + 8), gv(w1, kl + 9));
    W0f[g] = v;
}
// W2 Gram order (as R13/R14)
__global__ void frag_w2g(const float* __restrict__ W) {
    int g = blockIdx.x * 256 + threadIdx.x;
    if (g >= 8 * 8 * 40 * 32) return;
    int lane = g & 31;
    int t = g >> 5;
    int j = t % 40; t /= 40;
    int ch = t & 7, mt = t >> 3;
    int grp = lane >> 2, tig = lane & 3;
    uint4 v = make_uint4(0u, 0u, 0u, 0u);
    if (j < 39) {
        int r0 = mt * 16 + grp, r1 = r0 + 8;
        int c = j * 128 + ch * 16 + 2 * tig;
        v.x = pk16(W[(size_t)r0 * 4992 + c],     W[(size_t)r0 * 4992 + c + 1]);
        v.y = pk16(W[(size_t)r1 * 4992 + c],     W[(size_t)r1 * 4992 + c + 1]);
        v.z = pk16(W[(size_t)r0 * 4992 + c + 8], W[(size_t)r0 * 4992 + c + 9]);
        v.w = pk16(W[(size_t)r1 * 4992 + c + 8], W[(size_t)r1 * 4992 + c + 9]);
    }
    W2g[g] = v;
}

// -------------------- s-major mainloop (L0: NS=3, L1: NS=8) -----------------------
template <int NS>
__device__ __forceinline__ void layer_sj(
    const uint4* __restrict__ Wg,
    const uint32_t* xb,          // B-source (x0h for L0, xih for L1)
    const uint32_t* x0h,
    float acc[4][4][4],
    int lane, int hg, int n_base, int grp, int tig)
{
    const uint4* wbase = Wg + hg * 128 + lane;
    #pragma unroll 1
    for (int s = 0; s < NS; s++) {
        // Xi k-slice for this s: held in registers across the whole j sweep
        uint32_t xv0[4], xv1[4];
        const uint32_t* xr = xb + (s * 8 + tig) * XR2 + n_base + grp;
        #pragma unroll
        for (int nt = 0; nt < 4; nt++) {
            xv0[nt] = xr[nt * 8];
            xv1[nt] = xr[4 * XR2 + nt * 8];
        }

        const uint4* wp = wbase + s * (39 * 256);
        uint4 A[2][4];
        #pragma unroll
        for (int mt = 0; mt < 4; mt++) A[0][mt] = __ldg(wp + mt * 32);

        #pragma unroll 2
        for (int j = 0; j < 39; j++) {
            int p = j & 1;
            // prefetch next j's A frags (pad makes tail safe)
            #pragma unroll
            for (int mt = 0; mt < 4; mt++) A[p ^ 1][mt] = __ldg(wp + 256 + mt * 32);
            wp += 256;

            uint32_t sel = p ? 0x3232u : 0x1010u;
            const uint32_t* x0r = x0h + (j >> 1) * XR2 + n_base + grp;
            #pragma unroll
            for (int nt = 0; nt < 4; nt++) {
                uint32_t x0p = prmt(x0r[nt * 8], sel);
                uint32_t b0 = hmul2(x0p, xv0[nt]);
                uint32_t b1 = hmul2(x0p, xv1[nt]);
                #pragma unroll
                for (int mt = 0; mt < 4; mt++)
                    mma16(acc[mt][nt], A[p][mt], b0, b1);
            }
        }
    }
}

// -------------------- main fused kernel ---------------------------------------------
__global__ void __launch_bounds__(THREADS, 2)
cin_mma(const float* __restrict__ x,
        const uint4* __restrict__ w0f, const uint4* __restrict__ w1f,
        const uint4* __restrict__ w2g,
        const float* __restrict__ b0, const float* __restrict__ b1,
        const float* __restrict__ b2,
        float* __restrict__ out)
{
    extern __shared__ uint32_t smu[];
    uint32_t* x0h = smu;                       // 24 pair-rows x XR2
    uint32_t* xih = smu + 24 * XR2;            // 64 x XR2 (aliased as z1d 128 x ZSTR)
    uint32_t* z1d = xih;
    uint4*    x0d = (uint4*)(smu + 88 * XR2);            // 8 b x 3 jt x 32 lanes
    uint32_t* g2s = smu + 88 * XR2 + 8 * 96 * 4;         // 8 b x GSTR

    int tid = threadIdx.x;
    int lane = tid & 31, wid = tid >> 5;
    int grp = lane >> 2, tig = lane & 3;
    int hg = wid & 1;
    int h_base = hg * 64, n_base = (wid >> 1) * 32;
    int bbase = blockIdx.x * NBT;

    // k-pair-packed X0
    for (int i = tid; i < 24 * 128; i += THREADS) {
        int j2 = i >> 7, n = i & 127;
        int b = n >> 4, d = n & 15;
        const float* xb = x + (size_t)(bbase + b) * 624 + d;
        int j0 = 2 * j2, j1 = 2 * j2 + 1;
        float f0 = (j0 < 39) ? xb[j0 * 16] : 0.f;
        float f1 = (j1 < 39) ? xb[j1 * 16] : 0.f;
        x0h[j2 * XR2 + n] = pk16(f0, f1);
    }
    // d-pair-packed X0 A-frags (warp = batch)
    {
        const float* xb = x + (size_t)(bbase + wid) * 624;
        #pragma unroll
        for (int jt = 0; jt < 3; jt++) {
            int j0 = jt * 16 + grp, j1 = j0 + 8;
            float2 z2 = make_float2(0.f, 0.f);
            float2 a0 = (j0 < 39) ? *(const float2*)(xb + j0 * 16 + 2 * tig)     : z2;
            float2 a1 = (j0 < 39) ? *(const float2*)(xb + j0 * 16 + 2 * tig + 8) : z2;
            float2 c0 = (j1 < 39) ? *(const float2*)(xb + j1 * 16 + 2 * tig)     : z2;
            float2 c1 = (j1 < 39) ? *(const float2*)(xb + j1 * 16 + 2 * tig + 8) : z2;
            uint4 v;
            v.x = pk16(a0.x, a0.y);
            v.y = pk16(c0.x, c0.y);
            v.z = pk16(a1.x, a1.y);
            v.w = pk16(c1.x, c1.y);
            x0d[(wid * 3 + jt) * 32 + lane] = v;
        }
    }
    __syncthreads();

    float acc[4][4][4];
    int bcol0 = (wid >> 1) * 2;

    // ================= layers 0 and 1 =================
    #pragma unroll 1
    for (int l = 0; l < 2; l++) {
        #pragma unroll
        for (int mt = 0; mt < 4; mt++)
            #pragma unroll
            for (int nt = 0; nt < 4; nt++)
                #pragma unroll
                for (int q = 0; q < 4; q++) acc[mt][nt][q] = 0.f;

        const float* bias;
        if (l == 0) {
            bias = b0;
            layer_sj<3>(w0f, x0h, x0h, acc, lane, hg, n_base, grp, tig);
        } else {
            bias = b1;
            layer_sj<8>(w1f, xih, x0h, acc, lane, hg, n_base, grp, tig);
        }
        __syncthreads();   // all reads of xih done before overwrite

        #pragma unroll
        for (int mt = 0; mt < 4; mt++) {
            int h0 = h_base + mt * 16 + grp;
            float bv0 = __ldg(bias + h0), bv1 = __ldg(bias + h0 + 8);

            // d-sums
            #pragma unroll
            for (int half = 0; half < 2; half++) {
                int nt0 = half * 2;
                float s0 = acc[mt][nt0][0] + acc[mt][nt0][1]
                         + acc[mt][nt0 + 1][0] + acc[mt][nt0 + 1][1];
                float s1 = acc[mt][nt0][2] + acc[mt][nt0][3]
                         + acc[mt][nt0 + 1][2] + acc[mt][nt0 + 1][3];
                s0 += __shfl_xor_sync(0xffffffffu, s0, 1);
                s0 += __shfl_xor_sync(0xffffffffu, s0, 2);
                s1 += __shfl_xor_sync(0xffffffffu, s1, 1);
                s1 += __shfl_xor_sync(0xffffffffu, s1, 2);
                if (tig == 0) {
                    size_t ob = (size_t)(bbase + bcol0 + half) * 384 + l * 128;
                    out[ob + h0]     = s0 + 16.f * bv0;
                    out[ob + h0 + 8] = s1 + 16.f * bv1;
                }
            }

            if (l == 0) {
                // k-pair-packed Z0 -> xih
                #pragma unroll
                for (int nt = 0; nt < 4; nt++) {
                    int n = n_base + nt * 8 + 2 * tig;
                    float v0 = acc[mt][nt][0] + bv0;
                    float v1 = acc[mt][nt][1] + bv0;
                    float v2 = acc[mt][nt][2] + bv1;
                    float v3 = acc[mt][nt][3] + bv1;
                    float p0 = __shfl_down_sync(0xffffffffu, v0, 4);
                    float p1 = __shfl_down_sync(0xffffffffu, v1, 4);
                    float p2 = __shfl_down_sync(0xffffffffu, v2, 4);
                    float p3 = __shfl_down_sync(0xffffffffu, v3, 4);
                    if (!(grp & 1)) {
                        uint32_t* r0 = xih + (h0 >> 1) * XR2 + n;
                        uint32_t* r1 = xih + ((h0 + 8) >> 1) * XR2 + n;
                        r0[0] = pk16(v0, p0);
                        r0[1] = pk16(v1, p1);
                        r1[0] = pk16(v2, p2);
                        r1[1] = pk16(v3, p3);
                    }
                }
            } else {
                // d-pair-packed Z1 -> z1d
                #pragma unroll
                for (int nt = 0; nt < 4; nt++) {
                    int n = n_base + nt * 8 + 2 * tig;
                    int col = (n >> 4) * 8 + ((n >> 1) & 7);
                    z1d[h0 * ZSTR + col]       = pk16(acc[mt][nt][0] + bv0,
                                                      acc[mt][nt][1] + bv0);
                    z1d[(h0 + 8) * ZSTR + col] = pk16(acc[mt][nt][2] + bv1,
                                                      acc[mt][nt][3] + bv1);
                }
            }
        }
        __syncthreads();
    }

    // ================= layer 2 via Gram trick =================
    int mtw = wid;
    float fA[4] = {0.f, 0.f, 0.f, 0.f};
    float fB[4] = {0.f, 0.f, 0.f, 0.f};

    const uint4* wp2 = w2g + (size_t)(mtw * 8) * 40 * 32 + lane;
    uint4 R[8];
    #pragma unroll
    for (int r = 0; r < 8; r++) R[r] = __ldg(wp2 + r * 32);
    wp2 += 8 * 32;

    #pragma unroll 1
    for (int ch = 0; ch < 8; ch++) {
        // G-MMA: warp = batch wid
        #pragma unroll
        for (int jt = 0; jt < 3; jt++) {
            uint4 A = x0d[(wid * 3 + jt) * 32 + lane];
            #pragma unroll
            for (int ks = 0; ks < 2; ks++) {
                int kk = ch * 16 + ks * 8 + grp;
                uint32_t bb0 = z1d[kk * ZSTR + wid * 8 + tig];
                uint32_t bb1 = z1d[kk * ZSTR + wid * 8 + tig + 4];
                float g4[4] = {0.f, 0.f, 0.f, 0.f};
                mma16(g4, A, bb0, bb1);
                int c2l = (jt * 16 + grp) * 8 + ks * 4 + tig;
                g2s[wid * GSTR + c2l]      = pk16(g4[0], g4[1]);
                g2s[wid * GSTR + c2l + 64] = pk16(g4[2], g4[3]);
            }
        }
        __syncthreads();

        // final GEMM: 40 ksteps (j=39 zero)
        const uint32_t* gb = g2s + grp * GSTR + tig;
        #pragma unroll
        for (int j = 0; j < 40; j++) {
            uint4 A = R[j & 7];
            R[j & 7] = __ldg(wp2);
            wp2 += 32;
            uint32_t bb0 = gb[j * 8];
            uint32_t bb1 = gb[j * 8 + 4];
            if (j & 1) mma16(fB, A, bb0, bb1);
            else       mma16(fA, A, bb0, bb1);
        }
        __syncthreads();
    }

    // out2 epilogue
    {
        int h0 = mtw * 16 + grp;
        float bv0 = 16.f * __ldg(b2 + h0);
        float bv1 = 16.f * __ldg(b2 + h0 + 8);
        int bq = 2 * tig;
        size_t ob = (size_t)(bbase + bq) * 384 + 256;
        out[ob + h0]           = fA[0] + fB[0] + bv0;
        out[ob + 384 + h0]     = fA[1] + fB[1] + bv0;
        out[ob + h0 + 8]       = fA[2] + fB[2] + bv1;
        out[ob + 384 + h0 + 8] = fA[3] + fB[3] + bv1;
    }
}

// -------------------- launch ------------------------------------------------------------
extern "C" void kernel_launch(void* const* d_in, const int* in_sizes, int n_in,
                              void* d_out, int out_size) {
    const float* x  = (const float*)d_in[0];
    const float* W0 = (const float*)d_in[1];
    const float* b0 = (const float*)d_in[2];
    const float* W1 = (const float*)d_in[3];
    const float* b1 = (const float*)d_in[4];
    const float* W2 = (const float*)d_in[5];
    const float* b2 = (const float*)d_in[6];
    float* out = (float*)d_out;

    uint4 *w0f, *w1f, *w2g;
    cudaGetSymbolAddress((void**)&w0f, W0f);
    cudaGetSymbolAddress((void**)&w1f, W1f);
    cudaGetSymbolAddress((void**)&w2g, W2g);

    frag_w0<<<(3 * 39 * 256 + 255) / 256, 256>>>(W0);
    frag_w1<<<(8 * 39 * 256 + 255) / 256, 256>>>(W1, w1f);
    frag_w2g<<<(8 * 8 * 40 * 32 + 255) / 256, 256>>>(W2);

    // smem: x0h 24*XR2 + xih/z1d 64*XR2 + x0d 3072 + g2s 8*GSTR  (u32)
    int smem_u32 = 88 * XR2 + 8 * 96 * 4 + 8 * GSTR;
    int smem_bytes = smem_u32 * 4;   // 72,576 B -> 2 CTAs/SM
    cudaFuncSetAttribute(cin_mma, cudaFuncAttributeMaxDynamicSharedMemorySize, smem_bytes);
    cin_mma<<<4096 / NBT, THREADS, smem_bytes>>>(x, w0f, w1f, w2g, b0, b1, b2, out);
}